// round 15
// baseline (speedup 1.0000x reference)
#include <cuda_runtime.h>
#include <cstdint>

// Fixed shapes: B=64, C=3, H=W=256
#define NCAT    5
#define NB      64
#define E_ELEM  196608
#define SAMPLE_BYTES ((long long)E_ELEM * 4)   // 786432
#define TPB     256
#define GRID    384              // j-chunk = 512 floats = 2048 B
#define EPSF    1e-6f
#define NPART   15
#define NPAD    16

#define STAGES  6
#define CHUNK   2048             // bytes per array per stage (TPB * 8)
#define TXBYTES (3 * CHUNK)

__device__ float g_part[GRID * NPAD];
__device__ int   g_done = 0;     // self-resetting last-block counter

// -------- packed f32x2 helpers ----------------------------------------------
__device__ __forceinline__ unsigned long long f2_add(unsigned long long a, unsigned long long b) {
    unsigned long long r;
    asm("add.rn.f32x2 %0, %1, %2;" : "=l"(r) : "l"(a), "l"(b));
    return r;
}
__device__ __forceinline__ unsigned long long f2_fma(unsigned long long a, unsigned long long b,
                                                     unsigned long long c) {
    unsigned long long r;
    asm("fma.rn.f32x2 %0, %1, %2, %3;" : "=l"(r) : "l"(a), "l"(b), "l"(c));
    return r;
}
__device__ __forceinline__ void f2_unpack(unsigned long long v, float& lo, float& hi) {
    asm("mov.b64 {%0, %1}, %2;" : "=f"(lo), "=f"(hi) : "l"(v));
}

#define NEG1X2 0xBF800000BF800000ULL
#define ABSM2  0x7FFFFFFF7FFFFFFFULL

// -------- smem / mbarrier / bulk-copy helpers --------------------------------
__device__ __forceinline__ uint32_t smem_u32(const void* p) {
    uint32_t a;
    asm("{ .reg .u64 t; cvta.to.shared.u64 t, %1; cvt.u32.u64 %0, t; }" : "=r"(a) : "l"(p));
    return a;
}
__device__ __forceinline__ void mbar_init(uint32_t mbar, uint32_t count) {
    asm volatile("mbarrier.init.shared.b64 [%0], %1;" :: "r"(mbar), "r"(count) : "memory");
}
__device__ __forceinline__ void fence_async_shared() {
    asm volatile("fence.proxy.async.shared::cta;" ::: "memory");
}
__device__ __forceinline__ void mbar_expect_tx(uint32_t mbar, uint32_t bytes) {
    asm volatile("mbarrier.arrive.expect_tx.shared.b64 _, [%0], %1;"
                 :: "r"(mbar), "r"(bytes) : "memory");
}
__device__ __forceinline__ void mbar_arrive(uint32_t mbar) {
    asm volatile("mbarrier.arrive.release.cta.shared::cta.b64 _, [%0];"
                 :: "r"(mbar) : "memory");
}
__device__ __forceinline__ void mbar_wait(uint32_t mbar, uint32_t parity) {
    asm volatile(
        "{\n\t.reg .pred P;\n\t"
        "W%=:\n\t"
        "mbarrier.try_wait.parity.acquire.cta.shared::cta.b64 P, [%0], %1;\n\t"
        "@!P bra W%=;\n\t}"
        :: "r"(mbar), "r"(parity) : "memory");
}
__device__ __forceinline__ void bulk_cp(uint32_t dst_smem, const void* src, uint32_t mbar) {
    asm volatile(
        "cp.async.bulk.shared::cta.global.mbarrier::complete_tx::bytes [%0], [%1], %2, [%3];"
        :: "r"(dst_smem), "l"(src), "r"((uint32_t)CHUNK), "r"(mbar) : "memory");
}

// ---------------------------------------------------------------------------
// Uniform blocks: block = j-chunk of 512 floats; exactly 64 pipeline
// iterations over samples in NATURAL order (producer addresses are data-
// independent -> TMA starts at cycle 0). Per-category accumulation via a
// warp-uniform switch into 5 register pairs. Full/empty mbarriers, no block
// barrier in the loop.
// ---------------------------------------------------------------------------
__global__ void __launch_bounds__(TPB)
k_fused(const float* __restrict__ restored,
        const float* __restrict__ clean,
        const int*   __restrict__ de_id,
        const float* __restrict__ un,
        float*       __restrict__ out) {
    __shared__ int   s_id[NB];
    __shared__ int   s_cnt[NCAT];
    __shared__ float s_invc[NCAT];
    __shared__ float swarp[NPART][8];
    __shared__ int   s_last;
    __shared__ __align__(128) unsigned char s_data[STAGES][3][CHUNK];  // 36KB
    __shared__ __align__(8)  unsigned long long s_full[STAGES];
    __shared__ __align__(8)  unsigned long long s_empty[STAGES];

    const int tid = threadIdx.x;
    const long long jbyte = (long long)blockIdx.x * CHUNK;
    const char* __restrict__ bu = (const char*)un;
    const char* __restrict__ br = (const char*)restored;
    const char* __restrict__ bc = (const char*)clean;

    // ---- tid0: init barriers and launch the pipeline IMMEDIATELY ----
    if (tid == 0) {
#pragma unroll
        for (int s = 0; s < STAGES; ++s) {
            mbar_init(smem_u32(&s_full[s]), 1);
            mbar_init(smem_u32(&s_empty[s]), TPB / 32);
        }
        fence_async_shared();
#pragma unroll
        for (int p = 0; p < STAGES; ++p) {          // natural order: samples 0..5
            long long so = (long long)p * SAMPLE_BYTES + jbyte;
            uint32_t mb = smem_u32(&s_full[p]);
            mbar_expect_tx(mb, TXBYTES);
            bulk_cp(smem_u32(&s_data[p][0][0]), bu + so, mb);
            bulk_cp(smem_u32(&s_data[p][1][0]), br + so, mb);
            bulk_cp(smem_u32(&s_data[p][2][0]), bc + so, mb);
        }
    }
    // concurrent setup (overlaps TMA flight)
    if (tid < NB) {
        int c = de_id[tid];
        s_id[tid] = c < 0 ? 0 : (c >= NCAT ? NCAT - 1 : c);
    }
    __syncthreads();                                 // s_id + barriers visible
    if (tid < NCAT) {
        int cnt = 0;
#pragma unroll
        for (int b = 0; b < NB; ++b) cnt += (s_id[b] == tid);
        s_cnt[tid]  = cnt;
        s_invc[tid] = 1.0f / (float)(cnt > 0 ? cnt : 1);
    }
    __syncthreads();                                 // counts visible (for flush)

    // ---- main loop: 64 uniform iterations, natural sample order ----
    unsigned long long U0 = 0, U1 = 0, U2 = 0, U3 = 0, U4 = 0;
    unsigned long long A0 = 0, A1 = 0, A2 = 0, A3 = 0, A4 = 0;
    const int toff = tid * 8;
    const bool lane0 = (tid & 31) == 0;
    int stage = 0, phase = 0;
    for (int k = 0; k < NB; ++k) {
        mbar_wait(smem_u32(&s_full[stage]), phase);

        unsigned long long u = *(const unsigned long long*)&s_data[stage][0][toff];
        unsigned long long r = *(const unsigned long long*)&s_data[stage][1][toff];
        unsigned long long c = *(const unsigned long long*)&s_data[stage][2][toff];
        unsigned long long d = f2_fma(r, NEG1X2, c) & ABSM2;

        switch (s_id[k]) {                           // warp-uniform branch
            case 0: U0 = f2_add(U0, u); A0 = f2_add(A0, d); break;
            case 1: U1 = f2_add(U1, u); A1 = f2_add(A1, d); break;
            case 2: U2 = f2_add(U2, u); A2 = f2_add(A2, d); break;
            case 3: U3 = f2_add(U3, u); A3 = f2_add(A3, d); break;
            default: U4 = f2_add(U4, u); A4 = f2_add(A4, d); break;
        }

        __syncwarp();                                // all lanes consumed
        if (lane0) mbar_arrive(smem_u32(&s_empty[stage]));

        if (tid == 0 && k + STAGES < NB) {           // reissue (addresses static)
            mbar_wait(smem_u32(&s_empty[stage]), phase);
            long long so = (long long)(k + STAGES) * SAMPLE_BYTES + jbyte;
            uint32_t mb = smem_u32(&s_full[stage]);
            mbar_expect_tx(mb, TXBYTES);
            bulk_cp(smem_u32(&s_data[stage][0][0]), bu + so, mb);
            bulk_cp(smem_u32(&s_data[stage][1][0]), br + so, mb);
            bulk_cp(smem_u32(&s_data[stage][2][0]), bc + so, mb);
        }
        if (++stage == STAGES) { stage = 0; phase ^= 1; }
    }

    // ---- flush all 5 categories ----
    float vals[NPART];
    {
        unsigned long long Us[NCAT] = {U0, U1, U2, U3, U4};
        unsigned long long As[NCAT] = {A0, A1, A2, A3, A4};
#pragma unroll
        for (int c = 0; c < NCAT; ++c) {
            float u0, u1, a0, a1;
            f2_unpack(Us[c], u0, u1);
            f2_unpack(As[c], a0, a1);
            const float ic = s_invc[c];
            float s0 = 1.0f / (u0 * ic + EPSF);
            float s1 = 1.0f / (u1 * ic + EPSF);
            vals[c]      = fmaf(a1, s1, a0 * s0);
            vals[5 + c]  = a0 + a1;
            vals[10 + c] = u0 + u1;
        }
    }

    // ---- block reduce: warp shuffle, 8-warp combine ----
#pragma unroll
    for (int v = 0; v < NPART; ++v) {
#pragma unroll
        for (int o = 16; o > 0; o >>= 1)
            vals[v] += __shfl_xor_sync(0xffffffffu, vals[v], o);
    }
    if (lane0) {
        int w = tid >> 5;
#pragma unroll
        for (int v = 0; v < NPART; ++v) swarp[v][w] = vals[v];
    }
    __syncthreads();
    if (tid < NPART) {
        float s = 0.0f;
#pragma unroll
        for (int w = 0; w < 8; ++w) s += swarp[tid][w];
        g_part[blockIdx.x * NPAD + tid] = s;
    }

    // ---- last-block finalize (deterministic fixed-order reads) ----
    __threadfence();
    __syncthreads();
    if (tid == 0) s_last = (atomicAdd(&g_done, 1) == GRID - 1);
    __syncthreads();
    if (!s_last) return;
    __threadfence();

    {
        float acc[NPART];
#pragma unroll
        for (int v = 0; v < NPART; ++v) acc[v] = 0.0f;
        if (tid < 192) {                 // 384 rows, 2 per thread
            const float4* gp4 = reinterpret_cast<const float4*>(g_part);
#pragma unroll
            for (int rr = 0; rr < 2; ++rr) {
                int base = (tid * 2 + rr) * (NPAD / 4);
                float4 q0 = __ldcg(gp4 + base + 0);
                float4 q1 = __ldcg(gp4 + base + 1);
                float4 q2 = __ldcg(gp4 + base + 2);
                float4 q3 = __ldcg(gp4 + base + 3);
                acc[0] += q0.x;  acc[1] += q0.y;  acc[2]  += q0.z;  acc[3]  += q0.w;
                acc[4] += q1.x;  acc[5] += q1.y;  acc[6]  += q1.z;  acc[7]  += q1.w;
                acc[8] += q2.x;  acc[9] += q2.y;  acc[10] += q2.z;  acc[11] += q2.w;
                acc[12] += q3.x; acc[13] += q3.y; acc[14] += q3.z;
            }
        }
#pragma unroll
        for (int v = 0; v < NPART; ++v) {
#pragma unroll
            for (int o = 16; o > 0; o >>= 1)
                acc[v] += __shfl_xor_sync(0xffffffffu, acc[v], o);
        }
        if (lane0) {
            int w = tid >> 5;
#pragma unroll
            for (int v = 0; v < NPART; ++v) swarp[v][w] = acc[v];
        }
        __syncthreads();
        __shared__ float stot[NPART];
        if (tid < NPART) {
            float s = 0.0f;
#pragma unroll
            for (int w = 0; w < 8; ++w) s += swarp[tid][w];
            stot[tid] = s;
        }
        __syncthreads();

        if (tid == 0) {
            const float Ef = (float)E_ELEM;
            float totalsum = 0.0f, cum_sc = 0.0f, cumN = 0.0f;
            int num_ne = 0;
#pragma unroll
            for (int c = 0; c < NCAT; ++c) if (s_cnt[c] > 0) num_ne++;
#pragma unroll
            for (int c = 0; c < NCAT; ++c) {
                int   cnt  = s_cnt[c];
                bool  ne   = cnt > 0;
                float safe = (float)(cnt > 0 ? cnt : 1);
                float S_sc = stot[c];
                float S_ab = stot[5 + c];
                float S_un = stot[10 + c];

                cum_sc += S_sc;
                cumN   += (float)cnt * Ef;
                float cum_l1 = cum_sc / fmaxf(cumN, 1.0f);
                float un_num = S_un / (safe * Ef) + EPSF;
                float bn     = ne ? 2.0f * logf(un_num) : 0.0f;
                float unc    = ne ? cum_l1 : 0.0f;
                float old_l  = ne ? S_ab / (safe * Ef) : 0.0f;
                float cat_l  = unc + bn;
                totalsum += cat_l;

                out[1 + c]  = cat_l;
                out[6 + c]  = old_l;
                out[11 + c] = bn;
                out[16 + c] = unc;
            }
            out[0] = totalsum / (float)(num_ne > 0 ? num_ne : 1);
            g_done = 0;   // self-reset for graph replay
        }
    }
}

// ---------------------------------------------------------------------------
extern "C" void kernel_launch(void* const* d_in, const int* in_sizes, int n_in,
                              void* d_out, int out_size) {
    const float* restored = (const float*)d_in[0];
    const float* clean    = (const float*)d_in[1];
    const int*   de_id    = (const int*)d_in[2];
    const float* un       = (const float*)d_in[3];
    float*       out      = (float*)d_out;

    k_fused<<<GRID, TPB>>>(restored, clean, de_id, un, out);
}